// round 6
// baseline (speedup 1.0000x reference)
#include <cuda_runtime.h>
#include <math.h>

#define Bc   8
#define Vc   8
#define Nc   1000
#define Dc   256
#define Hc   8
#define KSc  32
#define BVc  64

#define NEG_INF __int_as_float(0xff800000)

// scratch (no allocations allowed)
__device__ float g_M[768 * 8];        // fused feature matrix: 7 feat coeffs + 1 flag coeff per row
__device__ float g_q[BVc * Dc];       // query[b,v,d]
__device__ float g_heads[BVc * Dc];   // concated heads [b,v, h*32+k]
__device__ float g_fq[BVc * Dc];      // final_Q
__device__ float g_logits[BVc * Nc];  // logits[b,v,n]
__device__ unsigned char g_mask[BVc * Nc];  // canonical 0/1 mask

// ---------------------------------------------------------------------------
// k_pre:
//   blocks   0..95  : M = pns1 + pns2[:, :768] @ pns1  (+ flag col)
//   blocks  96..159 : query[b,v] = fixed_context[b] + pcs @ [prev;veh]
//   blocks 160..223 : decode feasibility mask (auto-detect bool/int32/float32)
// ---------------------------------------------------------------------------
__global__ __launch_bounds__(256) void k_pre(
    const float* __restrict__ pns1,   // (768,7)
    const float* __restrict__ pns2,   // (768,769)
    const float* __restrict__ prev,   // (B,V,256)
    const float* __restrict__ veh,    // (B,V,8)
    const float* __restrict__ fc,     // (B,1,256)
    const float* __restrict__ pcs,    // (256,264)
    const void*  __restrict__ maskraw)
{
    int blk = blockIdx.x;
    int tid = threadIdx.x;
    if (blk < 96) {
        int warp = tid >> 5, lane = tid & 31;
        int r = blk * 8 + warp;            // row 0..767
        const float* p2row = pns2 + r * 769;
        float acc[7] = {0.f,0.f,0.f,0.f,0.f,0.f,0.f};
        for (int j = lane; j < 768; j += 32) {
            float p2 = p2row[j];
            const float* p1row = pns1 + j * 7;
            #pragma unroll
            for (int f = 0; f < 7; f++) acc[f] += p2 * p1row[f];
        }
        #pragma unroll
        for (int f = 0; f < 7; f++) {
            #pragma unroll
            for (int o = 16; o > 0; o >>= 1)
                acc[f] += __shfl_down_sync(0xffffffffu, acc[f], o);
        }
        if (lane == 0) {
            #pragma unroll
            for (int f = 0; f < 7; f++) g_M[r * 8 + f] = pns1[r * 7 + f] + acc[f];
            g_M[r * 8 + 7] = p2row[768];   // flag weight
        }
    } else if (blk < 160) {
        int bv = blk - 96;                 // 0..63
        int b = bv >> 3;
        __shared__ float cvs[264];
        for (int j = tid; j < 264; j += 256)
            cvs[j] = (j < 256) ? prev[bv * 256 + j] : veh[bv * 8 + (j - 256)];
        __syncthreads();
        const float* wrow = pcs + tid * 264;
        float acc = 0.f;
        for (int j = 0; j < 264; j++) acc += wrow[j] * cvs[j];
        g_q[bv * 256 + tid] = fc[b * 256 + tid] + acc;
    } else {
        // ---- mask decode with dtype auto-detection ----
        int bv = blk - 160;                // 0..63
        const unsigned int* w = (const unsigned int*)maskraw;
        bool all01 = true, bytes01 = true;
        #pragma unroll 8
        for (int i = 0; i < 64; i++) {
            unsigned int u = w[i];
            if (u > 1u) all01 = false;
            if (((u       ) & 0xffu) > 1u || ((u >>  8) & 0xffu) > 1u ||
                ((u >> 16) & 0xffu) > 1u || ((u >> 24) & 0xffu) > 1u)
                bytes01 = false;
        }
        // all words 0/1        -> int32 (bool bytes would almost surely exceed 1 in some word)
        // bytes all 0/1        -> bool (uint8)
        // else                 -> float32 (0x3f800000 present)
        int mode = all01 ? 1 : (bytes01 ? 0 : 2);
        for (int n = tid; n < Nc; n += 256) {
            int i = bv * Nc + n;
            unsigned char m;
            if (mode == 0)      m = ((const unsigned char*)maskraw)[i] ? 1 : 0;
            else if (mode == 1) m = ((const unsigned int*)maskraw)[i]  ? 1 : 0;
            else                m = (((const float*)maskraw)[i] != 0.0f) ? 1 : 0;
            g_mask[i] = m;
        }
    }
}

// ---------------------------------------------------------------------------
// k_attn: one block per (h,b). 1024 threads = 32 warps = 8 v-groups x 4 subs.
// Pass1: compat -> smem; block softmax over v*n=8000; Pass2: weighted V sum.
// ---------------------------------------------------------------------------
__global__ __launch_bounds__(1024) void k_attn(
    const float* __restrict__ ndf,             // (B,V,N,8)
    const float* __restrict__ gVs,             // (H,B,1,N,32)
    const float* __restrict__ gKs)             // (H,B,1,N,32)
{
    __shared__ float s_compat[Vc * Nc];        // 8000 floats (32 KB)
    __shared__ float s_red[1024];

    int hb = blockIdx.x;
    int h = hb >> 3, b = hb & 7;
    int tid = threadIdx.x;
    int warp = tid >> 5, lane = tid & 31;
    int v = warp >> 2, sub = warp & 3;
    int bv = b * 8 + v;

    float ck[8], cv8[8];
    {
        int rk = 256 + h * 32 + lane;          // gK rows
        int rv = h * 32 + lane;                // gV rows
        #pragma unroll
        for (int f = 0; f < 8; f++) { ck[f] = g_M[rk * 8 + f]; cv8[f] = g_M[rv * 8 + f]; }
    }
    float qv = g_q[bv * 256 + h * 32 + lane];
    const float inv_sqrt_ks = 0.17677669529663688f;   // 1/sqrt(32)

    const float4* fbase = (const float4*)(ndf + bv * Nc * 8);
    const float* gk = gKs + (h * Bc + b) * Nc * 32;
    const float* gv = gVs + (h * Bc + b) * Nc * 32;
    const unsigned char* mrow = g_mask + bv * Nc;

    // ---- pass 1: compat ----
    for (int n = sub; n < Nc; n += 4) {
        float4 f0 = fbase[n * 2];
        float4 f1 = fbase[n * 2 + 1];
        float val = gk[n * 32 + lane]
                  + ck[0]*f0.x + ck[1]*f0.y + ck[2]*f0.z + ck[3]*f0.w
                  + ck[4]*f1.x + ck[5]*f1.y + ck[6]*f1.z + ck[7]*f1.w;
        float p = qv * val;
        #pragma unroll
        for (int o = 16; o > 0; o >>= 1) p += __shfl_down_sync(0xffffffffu, p, o);
        if (lane == 0) {
            float c = p * inv_sqrt_ks;
            if (!mrow[n]) c = NEG_INF;
            s_compat[v * Nc + n] = c;
        }
    }
    __syncthreads();

    // ---- block max over 8000 ----
    float m = NEG_INF;
    for (int i = tid; i < Vc * Nc; i += 1024) m = fmaxf(m, s_compat[i]);
    s_red[tid] = m;
    __syncthreads();
    for (int s = 512; s > 0; s >>= 1) {
        if (tid < s) s_red[tid] = fmaxf(s_red[tid], s_red[tid + s]);
        __syncthreads();
    }
    m = s_red[0];
    __syncthreads();

    // ---- block sum of exp ----
    float ssum = 0.f;
    for (int i = tid; i < Vc * Nc; i += 1024) ssum += expf(s_compat[i] - m);
    s_red[tid] = ssum;
    __syncthreads();
    for (int s = 512; s > 0; s >>= 1) {
        if (tid < s) s_red[tid] += s_red[tid + s];
        __syncthreads();
    }
    float inv_s = 1.0f / s_red[0];
    __syncthreads();

    // ---- pass 2: weighted V sum ----
    float acc = 0.f;
    for (int n = sub; n < Nc; n += 4) {
        float w = expf(s_compat[v * Nc + n] - m) * inv_s;
        float4 f0 = fbase[n * 2];
        float4 f1 = fbase[n * 2 + 1];
        float val = gv[n * 32 + lane]
                  + cv8[0]*f0.x + cv8[1]*f0.y + cv8[2]*f0.z + cv8[3]*f0.w
                  + cv8[4]*f1.x + cv8[5]*f1.y + cv8[6]*f1.z + cv8[7]*f1.w;
        acc += w * val;
    }
    __syncthreads();
    s_red[tid] = acc;                       // [warp][lane]
    __syncthreads();
    if (warp < 8) {
        int vv = warp;
        float s = s_red[(vv * 4 + 0) * 32 + lane] + s_red[(vv * 4 + 1) * 32 + lane]
                + s_red[(vv * 4 + 2) * 32 + lane] + s_red[(vv * 4 + 3) * 32 + lane];
        g_heads[(b * 8 + vv) * 256 + h * 32 + lane] = s;
    }
}

// ---------------------------------------------------------------------------
// k_fq: final_Q[b,v] = po @ heads[b,v]
// ---------------------------------------------------------------------------
__global__ __launch_bounds__(256) void k_fq(const float* __restrict__ po)
{
    int bv = blockIdx.x;
    int d = threadIdx.x;
    __shared__ float hsm[256];
    hsm[d] = g_heads[bv * 256 + d];
    __syncthreads();
    const float* wrow = po + d * 256;
    float acc = 0.f;
    for (int j = 0; j < 256; j++) acc += wrow[j] * hsm[j];
    g_fq[bv * 256 + d] = acc;
}

// ---------------------------------------------------------------------------
// k_logits: logits[b,v,n] = tanh(fq . (lK_static + M_L feats)/16)*10 + logmask
// grid (64 bv, 4 tiles of 250 n). warp-per-n, lane covers 8 d-slices.
// ---------------------------------------------------------------------------
__global__ __launch_bounds__(256) void k_logits(
    const float* __restrict__ ndf,             // (B,V,N,8)
    const float* __restrict__ lKs)             // (B,1,N,256)
{
    int bv = blockIdx.x;
    int b = bv >> 3;
    int tile = blockIdx.y;                     // 0..3
    int tid = threadIdx.x, warp = tid >> 5, lane = tid & 31;

    __shared__ float fqsm[256];
    fqsm[tid] = g_fq[bv * 256 + tid];
    __syncthreads();

    float cl[8][8], fqv[8];
    #pragma unroll
    for (int i = 0; i < 8; i++) {
        int r = 512 + lane + 32 * i;           // lK rows
        #pragma unroll
        for (int f = 0; f < 8; f++) cl[i][f] = g_M[r * 8 + f];
        fqv[i] = fqsm[lane + 32 * i];
    }

    const float4* fbase = (const float4*)(ndf + bv * Nc * 8);
    const float* lk = lKs + b * Nc * 256;
    const unsigned char* mrow = g_mask + bv * Nc;

    int n0 = tile * 250;
    for (int n = n0 + warp; n < n0 + 250; n += 8) {
        float4 f0 = fbase[n * 2];
        float4 f1 = fbase[n * 2 + 1];
        float p = 0.f;
        #pragma unroll
        for (int i = 0; i < 8; i++) {
            float val = lk[n * 256 + lane + 32 * i]
                      + cl[i][0]*f0.x + cl[i][1]*f0.y + cl[i][2]*f0.z + cl[i][3]*f0.w
                      + cl[i][4]*f1.x + cl[i][5]*f1.y + cl[i][6]*f1.z + cl[i][7]*f1.w;
            p += fqv[i] * val;
        }
        #pragma unroll
        for (int o = 16; o > 0; o >>= 1) p += __shfl_down_sync(0xffffffffu, p, o);
        if (lane == 0) {
            float lg = tanhf(p * 0.0625f) * 10.0f;
            if (!mrow[n]) lg = NEG_INF;
            g_logits[bv * Nc + n] = lg;
        }
    }
}

// ---------------------------------------------------------------------------
// k_select: per-b softmax over v*n=8000, argmax (first-index tie-break),
// prob, logprob, entropy. Single block; writes 25 float32 outputs.
// ---------------------------------------------------------------------------
__global__ __launch_bounds__(1024) void k_select(float* __restrict__ out)
{
    __shared__ float s_v[1024];
    __shared__ int   s_i[1024];
    int tid = threadIdx.x;
    float ent = 0.f;

    for (int b = 0; b < 8; b++) {
        const float* lg = g_logits + b * 8000;

        float bm = NEG_INF; int bi = 0x7fffffff;
        for (int i = tid; i < 8000; i += 1024) {
            float x = lg[i];
            if (x > bm || (x == bm && i < bi)) { bm = x; bi = i; }
        }
        s_v[tid] = bm; s_i[tid] = bi;
        __syncthreads();
        for (int s = 512; s > 0; s >>= 1) {
            if (tid < s) {
                float xv = s_v[tid + s]; int xi = s_i[tid + s];
                if (xv > s_v[tid] || (xv == s_v[tid] && xi < s_i[tid])) {
                    s_v[tid] = xv; s_i[tid] = xi;
                }
            }
            __syncthreads();
        }
        float m = s_v[0];
        int op = s_i[0];
        __syncthreads();

        float ssum = 0.f;
        for (int i = tid; i < 8000; i += 1024) ssum += expf(lg[i] - m);
        s_v[tid] = ssum;
        __syncthreads();
        for (int s = 512; s > 0; s >>= 1) {
            if (tid < s) s_v[tid] += s_v[tid + s];
            __syncthreads();
        }
        float total = s_v[0];
        __syncthreads();

        if (tid == 0) {
            float prob    = 1.0f / total;       // exp(max - max) / sum
            float logprob = -logf(total);
            out[b]      = (float)(op / Nc);     // selected vehicle
            out[8 + b]  = (float)(op % Nc);     // selected node
            out[16 + b] = logprob;
            ent += prob * logprob;
        }
    }
    if (tid == 0) out[24] = -ent;               // entropy
}

// ---------------------------------------------------------------------------
extern "C" void kernel_launch(void* const* d_in, const int* in_sizes, int n_in,
                              void* d_out, int out_size)
{
    // metadata order (setup_inputs dict order):
    // 0 node_embeddings (unused numerically)
    const float* fc   = (const float*)d_in[1];   // fixed_context
    const float* prev = (const float*)d_in[2];   // prev_node_embeddings
    const float* ndf  = (const float*)d_in[3];   // node_dynamic_features
    const float* veh  = (const float*)d_in[4];   // vehicle_dynamic_features
    const float* gVs  = (const float*)d_in[5];   // glimpse_V_static
    const float* gKs  = (const float*)d_in[6];   // glimpse_K_static
    const float* lKs  = (const float*)d_in[7];   // logit_K_static
    const void*  mask = (const void*)d_in[8];    // feasibility_mask (dtype auto-detected)
    const float* pcs  = (const float*)d_in[9];
    const float* pns1 = (const float*)d_in[10];
    const float* pns2 = (const float*)d_in[11];
    const float* po   = (const float*)d_in[12];
    float* out = (float*)d_out;

    k_pre<<<224, 256>>>(pns1, pns2, prev, veh, fc, pcs, mask);
    k_attn<<<64, 1024>>>(ndf, gVs, gKs);
    k_fq<<<64, 256>>>(po);
    dim3 g6(64, 4);
    k_logits<<<g6, 256>>>(ndf, lKs);
    k_select<<<1, 1024>>>(out);
}